// round 15
// baseline (speedup 1.0000x reference)
#include <cuda_runtime.h>
#include <cuda_fp16.h>
#include <cstdint>

#define MAXN 50000
#define MAXE 800000
#define H 64
#define HC 16   // H/4 float4 chunks
#define EPS 1e-5f

// ------------------------- device scratch (no allocs allowed) -------------------------
// Zero-state invariant: g_degcnt, g_pool, g_sum, g_sumsq are zero at entry of every
// kernel_launch call (zero-initialized at module load; each replay restores them).
__device__ __align__(256) float  g_bufA[MAXN * H];   // layer output y (agg result, fp32)
__device__ __align__(256) __half g_hsH[MAXN * H];    // hs = (act @ W^T) * dinv, fp16
__device__ int   g_degcnt[MAXN];
__device__ int   g_rowptr[MAXN + 1];
__device__ int   g_cursor[MAXN];
__device__ int   g_csrsrc[MAXE];
__device__ float g_dinv[MAXN];
__device__ float g_sum[3 * H];     // per-layer BN stats
__device__ float g_sumsq[3 * H];
__device__ float g_pool[64 * H];
__device__ int   g_bsum[64];

// ------------------------- CSR build -------------------------
__global__ void hist_kernel(const int* __restrict__ ei, int e) {
    int i = blockIdx.x * blockDim.x + threadIdx.x;
    int stride = gridDim.x * blockDim.x;
    for (int t = i; t < e; t += stride) {
        int dst = ei[e + t];
        atomicAdd(&g_degcnt[dst], 1);
    }
}

__device__ __forceinline__ int block_incl_scan(int v, int tid) {
    __shared__ int ws[32];
    int lane = tid & 31, w = tid >> 5;
    #pragma unroll
    for (int o = 1; o < 32; o <<= 1) {
        int t = __shfl_up_sync(0xffffffffu, v, o);
        if (lane >= o) v += t;
    }
    if (lane == 31) ws[w] = v;
    __syncthreads();
    if (w == 0) {
        int s = ws[lane];
        #pragma unroll
        for (int o = 1; o < 32; o <<= 1) {
            int t = __shfl_up_sync(0xffffffffu, s, o);
            if (lane >= o) s += t;
        }
        ws[lane] = s;
    }
    __syncthreads();
    return v + (w > 0 ? ws[w - 1] : 0);
}

__global__ void scanA_kernel(int n) {
    int tid = threadIdx.x;
    int gid = blockIdx.x * 1024 + tid;
    int v = (gid < n) ? g_degcnt[gid] : 0;
    int incl = block_incl_scan(v, tid);
    if (gid < n) g_rowptr[gid] = incl - v;
    if (tid == 1023) g_bsum[blockIdx.x] = incl;
}

// scanC: adds block offsets, writes rowptr/cursor/dinv, restores g_degcnt to zero.
__global__ void scanC_kernel(int n, int e, int nb) {
    __shared__ int part[2];
    __shared__ int s_off;
    int tid = threadIdx.x;
    if (tid < 64) {
        int v = (tid < blockIdx.x && tid < nb) ? g_bsum[tid] : 0;
        #pragma unroll
        for (int o = 16; o; o >>= 1) v += __shfl_xor_sync(0xffffffffu, v, o);
        if ((tid & 31) == 0) part[tid >> 5] = v;
    }
    __syncthreads();
    if (tid == 0) s_off = part[0] + part[1];
    __syncthreads();
    int off = s_off;

    int gid = blockIdx.x * 1024 + tid;
    if (gid < n) {
        int d = g_degcnt[gid];
        int r = g_rowptr[gid] + off;
        g_rowptr[gid] = r;
        g_cursor[gid] = r;
        g_dinv[gid] = rsqrtf((float)d + 1.0f);
        g_degcnt[gid] = 0;
    }
    if (gid == 0) g_rowptr[n] = e;
}

__global__ void fill_csr_kernel(const int* __restrict__ ei, int e) {
    int i = blockIdx.x * blockDim.x + threadIdx.x;
    int stride = gridDim.x * blockDim.x;
    for (int t = i; t < e; t += stride) {
        int s = ei[t];
        int d = ei[e + t];
        int pos = atomicAdd(&g_cursor[d], 1);
        g_csrsrc[pos] = s;
    }
}

// ------------------------- tf32 MMA helpers -------------------------
__device__ __forceinline__ unsigned f2tf32(float f) {
    unsigned r;
    asm("cvt.rna.tf32.f32 %0, %1;" : "=r"(r) : "f"(f));
    return r;
}
__device__ __forceinline__ void mma_tf32(float c[4], unsigned a0, unsigned a1,
                                         unsigned a2, unsigned a3,
                                         unsigned b0, unsigned b1) {
    asm volatile(
        "mma.sync.aligned.m16n8k8.row.col.f32.tf32.tf32.f32 "
        "{%0,%1,%2,%3}, {%4,%5,%6,%7}, {%8,%9}, {%0,%1,%2,%3};"
        : "+f"(c[0]), "+f"(c[1]), "+f"(c[2]), "+f"(c[3])
        : "r"(a0), "r"(a1), "r"(a2), "r"(a3), "r"(b0), "r"(b1));
}

// ------------------------- GEMM (tensor core): hs = (act @ W^T) * dinv, store fp16 --------
// Block = 256 threads = 8 warps; block tile 128 rows x 64 cols; warp tile 32x32
// (warps 4x2). W staged ONCE for all K (w_sm[o][k], stride K+4). A staged per
// KT=16 chunk transposed (a_sm[k][row], stride 136). BN+ReLU folded into A
// staging; dinv at store; output converted to fp16. Accumulate fp32.
#define KT 16
#define AST 136
template <int K, bool BN, bool FROMX>
__global__ void __launch_bounds__(256) gemm_kernel(const float* __restrict__ in,
                                                   const float* __restrict__ W,
                                                   const float* __restrict__ gamma,
                                                   const float* __restrict__ beta,
                                                   int n, int layer, float fn) {
    constexpr int WST = K + 4;
    __shared__ unsigned a_sm[KT * AST];
    __shared__ unsigned w_sm[64 * WST];
    __shared__ float sScale[H], sShift[H];

    int tid = threadIdx.x;
    int row0 = blockIdx.x * 128;

    if (BN && tid < H) {
        float m = g_sum[layer * H + tid] / fn;
        float var = g_sumsq[layer * H + tid] / fn - m * m;
        float inv = rsqrtf(var + EPS);
        float sc = inv * gamma[tid];
        sScale[tid] = sc;
        sShift[tid] = beta[tid] - m * sc;
    }
    // stage ALL of W once
    #pragma unroll
    for (int it = 0; it < K / 16; it++) {
        int idx = it * 256 + tid;
        int o = idx / (K / 4);
        int kc = (idx % (K / 4)) << 2;
        float4 wv = *(const float4*)&W[o * K + kc];
        uint4 u;
        u.x = f2tf32(wv.x); u.y = f2tf32(wv.y);
        u.z = f2tf32(wv.z); u.w = f2tf32(wv.w);
        *(uint4*)&w_sm[o * WST + kc] = u;
    }
    __syncthreads();

    const float* src = FROMX ? in : g_bufA;

    int lane = tid & 31, warp = tid >> 5;
    int g = lane >> 2, t = lane & 3;
    int wm = warp & 3, wn = warp >> 2;
    int r0 = wm * 32;
    int c0 = wn * 32;

    float c[2][4][4];
    #pragma unroll
    for (int m = 0; m < 2; m++)
        #pragma unroll
        for (int nb = 0; nb < 4; nb++)
            #pragma unroll
            for (int i = 0; i < 4; i++) c[m][nb][i] = 0.f;

    #pragma unroll
    for (int kt = 0; kt < K; kt += KT) {
        #pragma unroll
        for (int it = 0; it < 2; it++) {
            int idx = it * 256 + tid;
            int row = idx & 127;
            int kc = (idx >> 7) << 2;
            int rg = row0 + row;
            float4 av = make_float4(0.f, 0.f, 0.f, 0.f);
            if (rg < n) {
                av = *(const float4*)&src[(size_t)rg * K + kt + kc];
                if (BN) {
                    float4 sc4 = *(const float4*)&sScale[kt + kc];
                    float4 sh4 = *(const float4*)&sShift[kt + kc];
                    av.x = fmaxf(fmaf(av.x, sc4.x, sh4.x), 0.f);
                    av.y = fmaxf(fmaf(av.y, sc4.y, sh4.y), 0.f);
                    av.z = fmaxf(fmaf(av.z, sc4.z, sh4.z), 0.f);
                    av.w = fmaxf(fmaf(av.w, sc4.w, sh4.w), 0.f);
                }
            }
            a_sm[(kc + 0) * AST + row] = f2tf32(av.x);
            a_sm[(kc + 1) * AST + row] = f2tf32(av.y);
            a_sm[(kc + 2) * AST + row] = f2tf32(av.z);
            a_sm[(kc + 3) * AST + row] = f2tf32(av.w);
        }
        __syncthreads();

        #pragma unroll
        for (int ks = 0; ks < KT; ks += 8) {
            unsigned a[2][4];
            #pragma unroll
            for (int m = 0; m < 2; m++) {
                int rb = r0 + m * 16;
                a[m][0] = a_sm[(ks + t) * AST + rb + g];
                a[m][1] = a_sm[(ks + t) * AST + rb + g + 8];
                a[m][2] = a_sm[(ks + t + 4) * AST + rb + g];
                a[m][3] = a_sm[(ks + t + 4) * AST + rb + g + 8];
            }
            #pragma unroll
            for (int nb = 0; nb < 4; nb++) {
                int o = c0 + nb * 8 + g;
                unsigned b0 = w_sm[o * WST + kt + ks + t];
                unsigned b1 = w_sm[o * WST + kt + ks + t + 4];
                mma_tf32(c[0][nb], a[0][0], a[0][1], a[0][2], a[0][3], b0, b1);
                mma_tf32(c[1][nb], a[1][0], a[1][1], a[1][2], a[1][3], b0, b1);
            }
        }
        __syncthreads();
    }

    // epilogue: frag c0=(g,2t) c1=(g,2t+1) c2=(g+8,2t) c3=(g+8,2t+1); dinv; fp16 store
    #pragma unroll
    for (int m = 0; m < 2; m++) {
        int rA = row0 + r0 + m * 16 + g;
        int rB = rA + 8;
        float dvA = (rA < n) ? g_dinv[rA] : 0.f;
        float dvB = (rB < n) ? g_dinv[rB] : 0.f;
        #pragma unroll
        for (int nb = 0; nb < 4; nb++) {
            int col = c0 + nb * 8 + 2 * t;
            if (rA < n) {
                __half2 h = __floats2half2_rn(c[m][nb][0] * dvA, c[m][nb][1] * dvA);
                *(__half2*)&g_hsH[(size_t)rA * H + col] = h;
            }
            if (rB < n) {
                __half2 h = __floats2half2_rn(c[m][nb][2] * dvB, c[m][nb][3] * dvB);
                *(__half2*)&g_hsH[(size_t)rB * H + col] = h;
            }
        }
    }
}

// ------------------------- Aggregation: y = dinv*(sum_nbr hs + hs_self) + bias ------------
// hs rows fp16 (128 B). 2-stream + unroll-4 (8 outstanding 128B gathers/warp).
// Warp per node; 16 lanes x uint2 (4 halves); fp32 accumulation.
__device__ __forceinline__ void acc_u2(float4& a, uint2 u) {
    float2 f0 = __half22float2(*reinterpret_cast<__half2*>(&u.x));
    float2 f1 = __half22float2(*reinterpret_cast<__half2*>(&u.y));
    a.x += f0.x; a.y += f0.y; a.z += f1.x; a.w += f1.y;
}
__global__ void __launch_bounds__(256) agg_kernel(const float* __restrict__ bias,
                                                  int n, int layer) {
    int tid = threadIdx.x;
    int gw = (blockIdx.x * blockDim.x + tid) >> 5;
    int nw = (gridDim.x * blockDim.x) >> 5;
    int lane = tid & 31, half = lane >> 4, q = lane & 15;

    const uint2* hs2 = (const uint2*)g_hsH;   // 16 uint2 per 64-half row
    float4* out4 = (float4*)g_bufA;

    float4 s1 = make_float4(0, 0, 0, 0);
    float4 s2 = make_float4(0, 0, 0, 0);
    float4 b4 = make_float4(bias[q * 4], bias[q * 4 + 1], bias[q * 4 + 2], bias[q * 4 + 3]);

    for (int node = gw; node < n; node += nw) {
        int rs = g_rowptr[node];
        int re = g_rowptr[node + 1];
        float4 acc = make_float4(0, 0, 0, 0);
        float4 aB = make_float4(0, 0, 0, 0);
        float4 aC = make_float4(0, 0, 0, 0), aD = make_float4(0, 0, 0, 0);
        if (half == 0) acc_u2(acc, hs2[(size_t)node * 16 + q]);   // self-loop

        int e2 = rs + half;
        for (; e2 + 6 < re; e2 += 8) {
            int i1 = g_csrsrc[e2];
            int i2 = g_csrsrc[e2 + 2];
            int i3 = g_csrsrc[e2 + 4];
            int i4 = g_csrsrc[e2 + 6];
            uint2 u1 = hs2[(size_t)i1 * 16 + q];
            uint2 u2 = hs2[(size_t)i2 * 16 + q];
            uint2 u3 = hs2[(size_t)i3 * 16 + q];
            uint2 u4 = hs2[(size_t)i4 * 16 + q];
            acc_u2(acc, u1); acc_u2(aB, u2); acc_u2(aC, u3); acc_u2(aD, u4);
        }
        if (e2 + 2 < re) {
            int i1 = g_csrsrc[e2];
            int i2 = g_csrsrc[e2 + 2];
            uint2 u1 = hs2[(size_t)i1 * 16 + q];
            uint2 u2 = hs2[(size_t)i2 * 16 + q];
            acc_u2(acc, u1); acc_u2(aB, u2);
            e2 += 4;
        }
        if (e2 < re) {
            uint2 u1 = hs2[(size_t)g_csrsrc[e2] * 16 + q];
            acc_u2(acc, u1);
        }
        acc.x += aB.x + aC.x + aD.x;
        acc.y += aB.y + aC.y + aD.y;
        acc.z += aB.z + aC.z + aD.z;
        acc.w += aB.w + aC.w + aD.w;

        acc.x += __shfl_xor_sync(0xffffffffu, acc.x, 16);
        acc.y += __shfl_xor_sync(0xffffffffu, acc.y, 16);
        acc.z += __shfl_xor_sync(0xffffffffu, acc.z, 16);
        acc.w += __shfl_xor_sync(0xffffffffu, acc.w, 16);
        if (half == 0) {
            float dv = g_dinv[node];
            float4 y;
            y.x = fmaf(acc.x, dv, b4.x);
            y.y = fmaf(acc.y, dv, b4.y);
            y.z = fmaf(acc.z, dv, b4.z);
            y.w = fmaf(acc.w, dv, b4.w);
            out4[(size_t)node * HC + q] = y;
            s1.x += y.x; s1.y += y.y; s1.z += y.z; s1.w += y.w;
            s2.x += y.x * y.x; s2.y += y.y * y.y; s2.z += y.z * y.z; s2.w += y.w * y.w;
        }
    }

    __shared__ float ssum[H], ssq[H];
    if (tid < H) { ssum[tid] = 0.f; ssq[tid] = 0.f; }
    __syncthreads();
    if (half == 0) {
        int c0 = q * 4;
        atomicAdd(&ssum[c0 + 0], s1.x); atomicAdd(&ssum[c0 + 1], s1.y);
        atomicAdd(&ssum[c0 + 2], s1.z); atomicAdd(&ssum[c0 + 3], s1.w);
        atomicAdd(&ssq[c0 + 0], s2.x);  atomicAdd(&ssq[c0 + 1], s2.y);
        atomicAdd(&ssq[c0 + 2], s2.z);  atomicAdd(&ssq[c0 + 3], s2.w);
    }
    __syncthreads();
    if (tid < H) {
        atomicAdd(&g_sum[layer * H + tid], ssum[tid]);
        atomicAdd(&g_sumsq[layer * H + tid], ssq[tid]);
    }
}

// ------------------------- pooling: segment mean over sorted batch -------------------------
__global__ void __launch_bounds__(256) pool_kernel(const int* __restrict__ batch,
                                                   const float* __restrict__ gamma,
                                                   const float* __restrict__ beta,
                                                   int n, float fn) {
    __shared__ float sScale[H], sShift[H];
    int tid = threadIdx.x;
    if (tid < H) {
        float m = g_sum[2 * H + tid] / fn;
        float var = g_sumsq[2 * H + tid] / fn - m * m;
        float inv = rsqrtf(var + EPS);
        float sc = inv * gamma[tid];
        sScale[tid] = sc;
        sShift[tid] = beta[tid] - m * sc;
    }
    __syncthreads();

    int g = blockIdx.x >> 3, sub = blockIdx.x & 7;
    int start, end;
    {
        int key = g;
        int lo = 0, hi = n;
        while (lo < hi) { int mid = (lo + hi) >> 1; if (batch[mid] < key) lo = mid + 1; else hi = mid; }
        start = lo;
        key = g + 1;
        lo = 0; hi = n;
        while (lo < hi) { int mid = (lo + hi) >> 1; if (batch[mid] < key) lo = mid + 1; else hi = mid; }
        end = lo;
    }
    int c = tid & 63;
    int rr = tid >> 6;  // 0..3
    float sc = sScale[c], sh = sShift[c];
    float cnt = fmaxf((float)(end - start), 1.f);
    float s = 0.f;
    for (int row = start + sub * 4 + rr; row < end; row += 32)
        s += fmaxf(fmaf(g_bufA[(size_t)row * H + c], sc, sh), 0.f);

    __shared__ float sm[256];
    sm[tid] = s;
    __syncthreads();
    if (tid < 128) sm[tid] += sm[tid + 128];
    __syncthreads();
    if (tid < 64) atomicAdd(&g_pool[g * H + tid], (sm[tid] + sm[tid + 64]) / cnt);
}

// ------------------------- final MLP (also restores zero invariants) ----------------------
__global__ void mlp_kernel(const float* __restrict__ l1w, const float* __restrict__ l1b,
                           const float* __restrict__ l2w, const float* __restrict__ l2b,
                           float* __restrict__ out) {
    int g = blockIdx.x, j = threadIdx.x;  // 32 threads
    __shared__ float p[H];
    p[j]      = g_pool[g * H + j];
    p[j + 32] = g_pool[g * H + j + 32];
    g_pool[g * H + j] = 0.f;
    g_pool[g * H + j + 32] = 0.f;
    if (g == 0) {
        for (int t = j; t < 3 * H; t += 32) { g_sum[t] = 0.f; g_sumsq[t] = 0.f; }
    }
    __syncwarp();
    float h = l1b[j];
    #pragma unroll
    for (int k = 0; k < H; k++) h = fmaf(p[k], l1w[j * H + k], h);
    h = fmaxf(h, 0.f);
    float v = h * l2w[j];
    #pragma unroll
    for (int o = 16; o; o >>= 1) v += __shfl_xor_sync(0xffffffffu, v, o);
    if (j == 0) out[g] = v + l2b[0];
}

// ------------------------- host launcher -------------------------
extern "C" void kernel_launch(void* const* d_in, const int* in_sizes, int n_in,
                              void* d_out, int out_size) {
    const float* x     = (const float*)d_in[0];
    const int*   ei    = (const int*)d_in[1];     // int32 on device (JAX x64 disabled)
    const int*   batch = (const int*)d_in[2];
    const float* W0  = (const float*)d_in[3];
    const float* b0  = (const float*)d_in[4];
    const float* gm0 = (const float*)d_in[5];
    const float* be0 = (const float*)d_in[6];
    const float* W1  = (const float*)d_in[7];
    const float* b1  = (const float*)d_in[8];
    const float* gm1 = (const float*)d_in[9];
    const float* be1 = (const float*)d_in[10];
    const float* W2  = (const float*)d_in[11];
    const float* b2  = (const float*)d_in[12];
    const float* gm2 = (const float*)d_in[13];
    const float* be2 = (const float*)d_in[14];
    const float* l1w = (const float*)d_in[15];
    const float* l1b = (const float*)d_in[16];
    const float* l2w = (const float*)d_in[17];
    const float* l2b = (const float*)d_in[18];

    int n = in_sizes[0] / 128;     // nodes
    int e = in_sizes[1] / 2;       // edges
    int G = out_size;              // graphs (64)

    int nb = (n + 1023) / 1024;
    int gg = (n + 127) / 128;
    float fn = (float)n;

    // CSR build; gemm0 at launch #4 so ncu captures it
    hist_kernel<<<(e + 255) / 256, 256>>>(ei, e);                                        // 1
    scanA_kernel<<<nb, 1024>>>(n);                                                       // 2
    scanC_kernel<<<nb, 1024>>>(n, e, nb);                                                // 3
    gemm_kernel<128, false, true><<<gg, 256>>>(x, W0, nullptr, nullptr, n, 0, fn);       // 4
    fill_csr_kernel<<<(e + 255) / 256, 256>>>(ei, e);                                    // 5

    agg_kernel<<<1024, 256>>>(b0, n, 0);                                                 // 6
    gemm_kernel<64, true, false><<<gg, 256>>>(nullptr, W1, gm0, be0, n, 0, fn);          // 7
    agg_kernel<<<1024, 256>>>(b1, n, 1);                                                 // 8
    gemm_kernel<64, true, false><<<gg, 256>>>(nullptr, W2, gm1, be1, n, 1, fn);          // 9
    agg_kernel<<<1024, 256>>>(b2, n, 2);                                                 // 10

    pool_kernel<<<G * 8, 256>>>(batch, gm2, be2, n, fn);                                 // 11
    mlp_kernel<<<G, 32>>>(l1w, l1b, l2w, l2b, (float*)d_out);                            // 12
}

// round 16
// speedup vs baseline: 1.0444x; 1.0444x over previous
#include <cuda_runtime.h>
#include <cuda_bf16.h>
#include <cstdint>

#define MAXN 50000
#define MAXE 800000
#define H 64
#define HC 16   // H/4 float4 chunks
#define EPS 1e-5f

// ------------------------- device scratch (no allocs allowed) -------------------------
// Zero-state invariant: g_degcnt, g_pool, g_sum, g_sumsq are zero at entry of every
// kernel_launch call (zero-initialized at module load; each replay restores them).
__device__ __align__(256) float g_bufA[MAXN * H];   // layer output y (agg result)
__device__ __align__(256) float g_bufB[MAXN * H];   // hs = (act @ W^T) * dinv
__device__ int   g_degcnt[MAXN];
__device__ int   g_rowptr[MAXN + 1];
__device__ int   g_cursor[MAXN];
__device__ int   g_csrsrc[MAXE];
__device__ float g_dinv[MAXN];
__device__ float g_sum[3 * H];     // per-layer BN stats
__device__ float g_sumsq[3 * H];
__device__ float g_pool[64 * H];
__device__ int   g_bsum[64];

// ------------------------- CSR build -------------------------
__global__ void hist_kernel(const int* __restrict__ ei, int e) {
    int i = blockIdx.x * blockDim.x + threadIdx.x;
    int stride = gridDim.x * blockDim.x;
    for (int t = i; t < e; t += stride) {
        int dst = ei[e + t];
        atomicAdd(&g_degcnt[dst], 1);
    }
}

__device__ __forceinline__ int block_incl_scan(int v, int tid) {
    __shared__ int ws[32];
    int lane = tid & 31, w = tid >> 5;
    #pragma unroll
    for (int o = 1; o < 32; o <<= 1) {
        int t = __shfl_up_sync(0xffffffffu, v, o);
        if (lane >= o) v += t;
    }
    if (lane == 31) ws[w] = v;
    __syncthreads();
    if (w == 0) {
        int s = ws[lane];
        #pragma unroll
        for (int o = 1; o < 32; o <<= 1) {
            int t = __shfl_up_sync(0xffffffffu, s, o);
            if (lane >= o) s += t;
        }
        ws[lane] = s;
    }
    __syncthreads();
    return v + (w > 0 ? ws[w - 1] : 0);
}

__global__ void scanA_kernel(int n) {
    int tid = threadIdx.x;
    int gid = blockIdx.x * 1024 + tid;
    int v = (gid < n) ? g_degcnt[gid] : 0;
    int incl = block_incl_scan(v, tid);
    if (gid < n) g_rowptr[gid] = incl - v;
    if (tid == 1023) g_bsum[blockIdx.x] = incl;
}

// scanC: adds block offsets, writes rowptr/cursor/dinv, restores g_degcnt to zero.
__global__ void scanC_kernel(int n, int e, int nb) {
    __shared__ int part[2];
    __shared__ int s_off;
    int tid = threadIdx.x;
    if (tid < 64) {
        int v = (tid < blockIdx.x && tid < nb) ? g_bsum[tid] : 0;
        #pragma unroll
        for (int o = 16; o; o >>= 1) v += __shfl_xor_sync(0xffffffffu, v, o);
        if ((tid & 31) == 0) part[tid >> 5] = v;
    }
    __syncthreads();
    if (tid == 0) s_off = part[0] + part[1];
    __syncthreads();
    int off = s_off;

    int gid = blockIdx.x * 1024 + tid;
    if (gid < n) {
        int d = g_degcnt[gid];
        int r = g_rowptr[gid] + off;
        g_rowptr[gid] = r;
        g_cursor[gid] = r;
        g_dinv[gid] = rsqrtf((float)d + 1.0f);
        g_degcnt[gid] = 0;
    }
    if (gid == 0) g_rowptr[n] = e;
}

// ------------------------- tf32 MMA helpers -------------------------
__device__ __forceinline__ unsigned f2tf32(float f) {
    unsigned r;
    asm("cvt.rna.tf32.f32 %0, %1;" : "=r"(r) : "f"(f));
    return r;
}
__device__ __forceinline__ void mma_tf32(float c[4], unsigned a0, unsigned a1,
                                         unsigned a2, unsigned a3,
                                         unsigned b0, unsigned b1) {
    asm volatile(
        "mma.sync.aligned.m16n8k8.row.col.f32.tf32.tf32.f32 "
        "{%0,%1,%2,%3}, {%4,%5,%6,%7}, {%8,%9}, {%0,%1,%2,%3};"
        : "+f"(c[0]), "+f"(c[1]), "+f"(c[2]), "+f"(c[3])
        : "r"(a0), "r"(a1), "r"(a2), "r"(a3), "r"(b0), "r"(b1));
}

// ------------------------- GEMM body (tensor core, reg-prefetch pipelined) -----------------
// Block = 256 threads = 8 warps; block tile 128x64; warp tile 32x32 (warps 4x2).
// W staged ONCE (w_sm[o][k], stride K+4). A staged per KT=16 chunk transposed
// (a_sm[k][row], stride 136), with NEXT chunk prefetched into registers while
// current chunk's MMAs run. BN+ReLU at STS; dinv at store. fp32 accumulate.
#define KT 16
#define AST 136
template <int K, bool BN, bool FROMX>
__device__ __forceinline__ void gemm_body(const float* __restrict__ in,
                                          const float* __restrict__ W,
                                          const float* __restrict__ gamma,
                                          const float* __restrict__ beta,
                                          int n, int layer, float fn, int blk) {
    constexpr int WST = K + 4;
    __shared__ unsigned a_sm[KT * AST];
    __shared__ unsigned w_sm[64 * WST];
    __shared__ float sScale[H], sShift[H];

    int tid = threadIdx.x;
    int row0 = blk * 128;

    if (BN && tid < H) {
        float m = g_sum[layer * H + tid] / fn;
        float var = g_sumsq[layer * H + tid] / fn - m * m;
        float inv = rsqrtf(var + EPS);
        float sc = inv * gamma[tid];
        sScale[tid] = sc;
        sShift[tid] = beta[tid] - m * sc;
    }
    // stage ALL of W once
    #pragma unroll
    for (int it = 0; it < K / 16; it++) {
        int idx = it * 256 + tid;
        int o = idx / (K / 4);
        int kc = (idx % (K / 4)) << 2;
        float4 wv = *(const float4*)&W[o * K + kc];
        uint4 u;
        u.x = f2tf32(wv.x); u.y = f2tf32(wv.y);
        u.z = f2tf32(wv.z); u.w = f2tf32(wv.w);
        *(uint4*)&w_sm[o * WST + kc] = u;
    }

    const float* src = FROMX ? in : g_bufA;

    int lane = tid & 31, warp = tid >> 5;
    int g = lane >> 2, t = lane & 3;
    int wm = warp & 3, wn = warp >> 2;
    int r0 = wm * 32;
    int c0 = wn * 32;

    // per-thread staging coordinates
    int rowA[2], kcA[2], rgA[2];
    #pragma unroll
    for (int it = 0; it < 2; it++) {
        int idx = it * 256 + tid;
        rowA[it] = idx & 127;
        kcA[it] = (idx >> 7) << 2;
        rgA[it] = row0 + rowA[it];
    }

    float c[2][4][4];
    #pragma unroll
    for (int m = 0; m < 2; m++)
        #pragma unroll
        for (int nb = 0; nb < 4; nb++)
            #pragma unroll
            for (int i = 0; i < 4; i++) c[m][nb][i] = 0.f;

    // prefetch chunk 0 into registers
    float4 pf[2];
    #pragma unroll
    for (int it = 0; it < 2; it++)
        pf[it] = (rgA[it] < n) ? *(const float4*)&src[(size_t)rgA[it] * K + kcA[it]]
                               : make_float4(0.f, 0.f, 0.f, 0.f);
    __syncthreads();   // covers W staging + sScale

    #pragma unroll
    for (int kt = 0; kt < K; kt += KT) {
        // STS current chunk (BN+ReLU+cvt applied here)
        #pragma unroll
        for (int it = 0; it < 2; it++) {
            float4 av = pf[it];
            int kc = kcA[it];
            if (BN) {
                float4 sc4 = *(const float4*)&sScale[kt + kc];
                float4 sh4 = *(const float4*)&sShift[kt + kc];
                av.x = fmaxf(fmaf(av.x, sc4.x, sh4.x), 0.f);
                av.y = fmaxf(fmaf(av.y, sc4.y, sh4.y), 0.f);
                av.z = fmaxf(fmaf(av.z, sc4.z, sh4.z), 0.f);
                av.w = fmaxf(fmaf(av.w, sc4.w, sh4.w), 0.f);
            }
            a_sm[(kc + 0) * AST + rowA[it]] = f2tf32(av.x);
            a_sm[(kc + 1) * AST + rowA[it]] = f2tf32(av.y);
            a_sm[(kc + 2) * AST + rowA[it]] = f2tf32(av.z);
            a_sm[(kc + 3) * AST + rowA[it]] = f2tf32(av.w);
        }
        __syncthreads();

        // prefetch NEXT chunk (LDGs in flight during the MMAs below)
        if (kt + KT < K) {
            #pragma unroll
            for (int it = 0; it < 2; it++)
                pf[it] = (rgA[it] < n)
                    ? *(const float4*)&src[(size_t)rgA[it] * K + kt + KT + kcA[it]]
                    : make_float4(0.f, 0.f, 0.f, 0.f);
        }

        #pragma unroll
        for (int ks = 0; ks < KT; ks += 8) {
            unsigned a[2][4];
            #pragma unroll
            for (int m = 0; m < 2; m++) {
                int rb = r0 + m * 16;
                a[m][0] = a_sm[(ks + t) * AST + rb + g];
                a[m][1] = a_sm[(ks + t) * AST + rb + g + 8];
                a[m][2] = a_sm[(ks + t + 4) * AST + rb + g];
                a[m][3] = a_sm[(ks + t + 4) * AST + rb + g + 8];
            }
            #pragma unroll
            for (int nb = 0; nb < 4; nb++) {
                int o = c0 + nb * 8 + g;
                unsigned b0 = w_sm[o * WST + kt + ks + t];
                unsigned b1 = w_sm[o * WST + kt + ks + t + 4];
                mma_tf32(c[0][nb], a[0][0], a[0][1], a[0][2], a[0][3], b0, b1);
                mma_tf32(c[1][nb], a[1][0], a[1][1], a[1][2], a[1][3], b0, b1);
            }
        }
        __syncthreads();
    }

    // epilogue: frag c0=(g,2t) c1=(g,2t+1) c2=(g+8,2t) c3=(g+8,2t+1); scale by dinv
    #pragma unroll
    for (int m = 0; m < 2; m++) {
        int rA = row0 + r0 + m * 16 + g;
        int rB = rA + 8;
        float dvA = (rA < n) ? g_dinv[rA] : 0.f;
        float dvB = (rB < n) ? g_dinv[rB] : 0.f;
        #pragma unroll
        for (int nb = 0; nb < 4; nb++) {
            int col = c0 + nb * 8 + 2 * t;
            if (rA < n) {
                float2 v = make_float2(c[m][nb][0] * dvA, c[m][nb][1] * dvA);
                *(float2*)&g_bufB[(size_t)rA * H + col] = v;
            }
            if (rB < n) {
                float2 v = make_float2(c[m][nb][2] * dvB, c[m][nb][3] * dvB);
                *(float2*)&g_bufB[(size_t)rB * H + col] = v;
            }
        }
    }
}

// Fused layer-0 kernel: first gemmBlocks blocks do the K=128 GEMM; remaining blocks
// grid-stride the CSR scatter fill (independent work, overlaps GEMM stalls).
__global__ void __launch_bounds__(256) gemm0_fill_kernel(const float* __restrict__ x,
                                                         const float* __restrict__ W0,
                                                         const int* __restrict__ ei,
                                                         int n, int e, int gemmBlocks) {
    if ((int)blockIdx.x < gemmBlocks) {
        gemm_body<128, false, true>(x, W0, nullptr, nullptr, n, 0, 1.f, blockIdx.x);
    } else {
        int nfb = gridDim.x - gemmBlocks;
        int i = (blockIdx.x - gemmBlocks) * blockDim.x + threadIdx.x;
        int stride = nfb * blockDim.x;
        for (int t = i; t < e; t += stride) {
            int s = ei[t];
            int d = ei[e + t];
            int pos = atomicAdd(&g_cursor[d], 1);
            g_csrsrc[pos] = s;
        }
    }
}

__global__ void __launch_bounds__(256) gemmBN_kernel(const float* __restrict__ W,
                                                     const float* __restrict__ gamma,
                                                     const float* __restrict__ beta,
                                                     int n, int layer, float fn) {
    gemm_body<64, true, false>(nullptr, W, gamma, beta, n, layer, fn, blockIdx.x);
}

// ------------------------- Aggregation: y = dinv*(sum_nbr hs + hs_self) + bias ------------
// 2-stream + unroll-4 (8 outstanding gathers/warp), fp32 hs. Warp per node.
__global__ void __launch_bounds__(256) agg_kernel(const float* __restrict__ bias,
                                                  int n, int layer) {
    int tid = threadIdx.x;
    int gw = (blockIdx.x * blockDim.x + tid) >> 5;
    int nw = (gridDim.x * blockDim.x) >> 5;
    int lane = tid & 31, half = lane >> 4, q = lane & 15;

    const float4* hs4 = (const float4*)g_bufB;
    float4* out4 = (float4*)g_bufA;

    float4 s1 = make_float4(0, 0, 0, 0);
    float4 s2 = make_float4(0, 0, 0, 0);
    float4 b4 = make_float4(bias[q * 4], bias[q * 4 + 1], bias[q * 4 + 2], bias[q * 4 + 3]);

    for (int node = gw; node < n; node += nw) {
        int rs = g_rowptr[node];
        int re = g_rowptr[node + 1];
        float4 acc, aB = make_float4(0, 0, 0, 0);
        float4 aC = make_float4(0, 0, 0, 0), aD = make_float4(0, 0, 0, 0);
        if (half == 0) acc = hs4[(size_t)node * HC + q];   // self-loop term
        else           acc = make_float4(0, 0, 0, 0);

        int e2 = rs + half;
        for (; e2 + 6 < re; e2 += 8) {
            int i1 = g_csrsrc[e2];
            int i2 = g_csrsrc[e2 + 2];
            int i3 = g_csrsrc[e2 + 4];
            int i4 = g_csrsrc[e2 + 6];
            float4 v1 = hs4[(size_t)i1 * HC + q];
            float4 v2 = hs4[(size_t)i2 * HC + q];
            float4 v3 = hs4[(size_t)i3 * HC + q];
            float4 v4 = hs4[(size_t)i4 * HC + q];
            acc.x += v1.x; acc.y += v1.y; acc.z += v1.z; acc.w += v1.w;
            aB.x += v2.x;  aB.y += v2.y;  aB.z += v2.z;  aB.w += v2.w;
            aC.x += v3.x;  aC.y += v3.y;  aC.z += v3.z;  aC.w += v3.w;
            aD.x += v4.x;  aD.y += v4.y;  aD.z += v4.z;  aD.w += v4.w;
        }
        if (e2 + 2 < re) {
            int i1 = g_csrsrc[e2];
            int i2 = g_csrsrc[e2 + 2];
            float4 v1 = hs4[(size_t)i1 * HC + q];
            float4 v2 = hs4[(size_t)i2 * HC + q];
            acc.x += v1.x; acc.y += v1.y; acc.z += v1.z; acc.w += v1.w;
            aB.x += v2.x;  aB.y += v2.y;  aB.z += v2.z;  aB.w += v2.w;
            e2 += 4;
        }
        if (e2 < re) {
            int i1 = g_csrsrc[e2];
            float4 v1 = hs4[(size_t)i1 * HC + q];
            acc.x += v1.x; acc.y += v1.y; acc.z += v1.z; acc.w += v1.w;
        }
        acc.x += aB.x + aC.x + aD.x;
        acc.y += aB.y + aC.y + aD.y;
        acc.z += aB.z + aC.z + aD.z;
        acc.w += aB.w + aC.w + aD.w;

        acc.x += __shfl_xor_sync(0xffffffffu, acc.x, 16);
        acc.y += __shfl_xor_sync(0xffffffffu, acc.y, 16);
        acc.z += __shfl_xor_sync(0xffffffffu, acc.z, 16);
        acc.w += __shfl_xor_sync(0xffffffffu, acc.w, 16);
        if (half == 0) {
            float dv = g_dinv[node];
            float4 y;
            y.x = fmaf(acc.x, dv, b4.x);
            y.y = fmaf(acc.y, dv, b4.y);
            y.z = fmaf(acc.z, dv, b4.z);
            y.w = fmaf(acc.w, dv, b4.w);
            out4[(size_t)node * HC + q] = y;
            s1.x += y.x; s1.y += y.y; s1.z += y.z; s1.w += y.w;
            s2.x += y.x * y.x; s2.y += y.y * y.y; s2.z += y.z * y.z; s2.w += y.w * y.w;
        }
    }

    __shared__ float ssum[H], ssq[H];
    if (tid < H) { ssum[tid] = 0.f; ssq[tid] = 0.f; }
    __syncthreads();
    if (half == 0) {
        int c0 = q * 4;
        atomicAdd(&ssum[c0 + 0], s1.x); atomicAdd(&ssum[c0 + 1], s1.y);
        atomicAdd(&ssum[c0 + 2], s1.z); atomicAdd(&ssum[c0 + 3], s1.w);
        atomicAdd(&ssq[c0 + 0], s2.x);  atomicAdd(&ssq[c0 + 1], s2.y);
        atomicAdd(&ssq[c0 + 2], s2.z);  atomicAdd(&ssq[c0 + 3], s2.w);
    }
    __syncthreads();
    if (tid < H) {
        atomicAdd(&g_sum[layer * H + tid], ssum[tid]);
        atomicAdd(&g_sumsq[layer * H + tid], ssq[tid]);
    }
}

// ------------------------- pooling: segment mean over sorted batch -------------------------
__global__ void __launch_bounds__(256) pool_kernel(const int* __restrict__ batch,
                                                   const float* __restrict__ gamma,
                                                   const float* __restrict__ beta,
                                                   int n, float fn) {
    __shared__ float sScale[H], sShift[H];
    int tid = threadIdx.x;
    if (tid < H) {
        float m = g_sum[2 * H + tid] / fn;
        float var = g_sumsq[2 * H + tid] / fn - m * m;
        float inv = rsqrtf(var + EPS);
        float sc = inv * gamma[tid];
        sScale[tid] = sc;
        sShift[tid] = beta[tid] - m * sc;
    }
    __syncthreads();

    int g = blockIdx.x >> 3, sub = blockIdx.x & 7;
    int start, end;
    {
        int key = g;
        int lo = 0, hi = n;
        while (lo < hi) { int mid = (lo + hi) >> 1; if (batch[mid] < key) lo = mid + 1; else hi = mid; }
        start = lo;
        key = g + 1;
        lo = 0; hi = n;
        while (lo < hi) { int mid = (lo + hi) >> 1; if (batch[mid] < key) lo = mid + 1; else hi = mid; }
        end = lo;
    }
    int c = tid & 63;
    int rr = tid >> 6;  // 0..3
    float sc = sScale[c], sh = sShift[c];
    float cnt = fmaxf((float)(end - start), 1.f);
    float s = 0.f;
    for (int row = start + sub * 4 + rr; row < end; row += 32)
        s += fmaxf(fmaf(g_bufA[(size_t)row * H + c], sc, sh), 0.f);

    __shared__ float sm[256];
    sm[tid] = s;
    __syncthreads();
    if (tid < 128) sm[tid] += sm[tid + 128];
    __syncthreads();
    if (tid < 64) atomicAdd(&g_pool[g * H + tid], (sm[tid] + sm[tid + 64]) / cnt);
}

// ------------------------- final MLP (also restores zero invariants) ----------------------
__global__ void mlp_kernel(const float* __restrict__ l1w, const float* __restrict__ l1b,
                           const float* __restrict__ l2w, const float* __restrict__ l2b,
                           float* __restrict__ out) {
    int g = blockIdx.x, j = threadIdx.x;  // 32 threads
    __shared__ float p[H];
    p[j]      = g_pool[g * H + j];
    p[j + 32] = g_pool[g * H + j + 32];
    g_pool[g * H + j] = 0.f;
    g_pool[g * H + j + 32] = 0.f;
    if (g == 0) {
        for (int t = j; t < 3 * H; t += 32) { g_sum[t] = 0.f; g_sumsq[t] = 0.f; }
    }
    __syncwarp();
    float h = l1b[j];
    #pragma unroll
    for (int k = 0; k < H; k++) h = fmaf(p[k], l1w[j * H + k], h);
    h = fmaxf(h, 0.f);
    float v = h * l2w[j];
    #pragma unroll
    for (int o = 16; o; o >>= 1) v += __shfl_xor_sync(0xffffffffu, v, o);
    if (j == 0) out[g] = v + l2b[0];
}

// ------------------------- host launcher -------------------------
extern "C" void kernel_launch(void* const* d_in, const int* in_sizes, int n_in,
                              void* d_out, int out_size) {
    const float* x     = (const float*)d_in[0];
    const int*   ei    = (const int*)d_in[1];     // int32 on device (JAX x64 disabled)
    const int*   batch = (const int*)d_in[2];
    const float* W0  = (const float*)d_in[3];
    const float* b0  = (const float*)d_in[4];
    const float* gm0 = (const float*)d_in[5];
    const float* be0 = (const float*)d_in[6];
    const float* W1  = (const float*)d_in[7];
    const float* b1  = (const float*)d_in[8];
    const float* gm1 = (const float*)d_in[9];
    const float* be1 = (const float*)d_in[10];
    const float* W2  = (const float*)d_in[11];
    const float* b2  = (const float*)d_in[12];
    const float* gm2 = (const float*)d_in[13];
    const float* be2 = (const float*)d_in[14];
    const float* l1w = (const float*)d_in[15];
    const float* l1b = (const float*)d_in[16];
    const float* l2w = (const float*)d_in[17];
    const float* l2b = (const float*)d_in[18];

    int n = in_sizes[0] / 128;     // nodes
    int e = in_sizes[1] / 2;       // edges
    int G = out_size;              // graphs (64)

    int nb = (n + 1023) / 1024;
    int gg = (n + 127) / 128;      // gemm blocks (391)
    int fillBlocks = 192;
    float fn = (float)n;

    hist_kernel<<<(e + 255) / 256, 256>>>(ei, e);                                        // 1
    scanA_kernel<<<nb, 1024>>>(n);                                                       // 2
    scanC_kernel<<<nb, 1024>>>(n, e, nb);                                                // 3
    // fused: gemm0 + CSR fill (independent given scanC) — captured launch #4
    gemm0_fill_kernel<<<gg + fillBlocks, 256>>>(x, W0, ei, n, e, gg);                    // 4

    agg_kernel<<<1024, 256>>>(b0, n, 0);                                                 // 5
    gemmBN_kernel<<<gg, 256>>>(W1, gm0, be0, n, 0, fn);                                  // 6
    agg_kernel<<<1024, 256>>>(b1, n, 1);                                                 // 7
    gemmBN_kernel<<<gg, 256>>>(W2, gm1, be1, n, 1, fn);                                  // 8
    agg_kernel<<<1024, 256>>>(b2, n, 2);                                                 // 9

    pool_kernel<<<G * 8, 256>>>(batch, gm2, be2, n, fn);                                 // 10
    mlp_kernel<<<G, 32>>>(l1w, l1b, l2w, l2b, (float*)d_out);                            // 11
}